// round 15
// baseline (speedup 1.0000x reference)
#include <cuda_runtime.h>
#include <cuda_bf16.h>
#include <stdint.h>
#include <math.h>

#define BATCH 4
#define SEQL  4096
#define KQL   4096
#define HID   1024
#define NT    ((size_t)BATCH * KQL * HID)   // 16,777,216 els per qkv plane
#define NW    ((size_t)HID * HID)           // 1,048,576 els per weight

// ---------------- device scratch (allocation-free rule: __device__ globals) ----
__device__ __nv_bfloat16 g_xh[3 * NT];      // stacked inputs (q,k,v) hi
__device__ __nv_bfloat16 g_xl[3 * NT];
__device__ __nv_bfloat16 g_wh[3 * NW];      // stacked weights hi
__device__ __nv_bfloat16 g_wl[3 * NW];
__device__ float         g_bias[3 * HID];   // stacked biases
__device__ __nv_bfloat16 g_qkvh[3 * NT];    // stacked projected q,k,v hi
__device__ __nv_bfloat16 g_qkvl[3 * NT];
__device__ __nv_bfloat16 g_vth[(size_t)BATCH * HID * SEQL];
__device__ __nv_bfloat16 g_vtl[(size_t)BATCH * HID * SEQL];
__device__ __nv_bfloat16 g_ath[(size_t)BATCH * KQL * SEQL];
__device__ __nv_bfloat16 g_atl[(size_t)BATCH * KQL * SEQL];
__device__ float         g_statM[(size_t)BATCH * KQL];
__device__ float         g_statI[(size_t)BATCH * KQL];

// ---------------- helpers ------------------------------------------------------
__device__ __forceinline__ uint32_t s2u(const void* p) {
    return (uint32_t)__cvta_generic_to_shared(p);
}
__device__ __forceinline__ void cpasync16(uint32_t dst, const void* src) {
    asm volatile("cp.async.cg.shared.global [%0], [%1], 16;" :: "r"(dst), "l"(src));
}
__device__ __forceinline__ void cp_commit() {
    asm volatile("cp.async.commit_group;" ::: "memory");
}
__device__ __forceinline__ void cp_wait1() {
    asm volatile("cp.async.wait_group 1;" ::: "memory");
}
__device__ __forceinline__ void cp_wait0() {
    asm volatile("cp.async.wait_group 0;" ::: "memory");
}
// D += A * B  (m16n8k16, row.col, bf16 in / f32 accum)
__device__ __forceinline__ void mma16816(float c[4], const uint32_t a[4], const uint32_t* b) {
    asm volatile(
        "mma.sync.aligned.m16n8k16.row.col.f32.bf16.bf16.f32 "
        "{%0,%1,%2,%3}, {%4,%5,%6,%7}, {%8,%9}, {%0,%1,%2,%3};"
        : "+f"(c[0]), "+f"(c[1]), "+f"(c[2]), "+f"(c[3])
        : "r"(a[0]), "r"(a[1]), "r"(a[2]), "r"(a[3]), "r"(b[0]), "r"(b[1]));
}
__device__ __forceinline__ void ldsm4(uint32_t r[4], uint32_t saddr) {
    asm volatile("ldmatrix.sync.aligned.m8n8.x4.shared.b16 {%0,%1,%2,%3}, [%4];"
                 : "=r"(r[0]), "=r"(r[1]), "=r"(r[2]), "=r"(r[3]) : "r"(saddr));
}

// smem geometry: 4 planes (Ah, Al, Bh, Bl), each 128 rows x KC bf16, padded
#define KC      32
#define RS      40                    // padded row stride in bf16 (80B)
#define PLANE_E (128 * RS)
#define STAGE_E (4 * PLANE_E)
#define NSTAGE  2
#define GEMM_SMEM (NSTAGE * STAGE_E * 2)   // 81920 bytes -> 2 CTAs/SM

// ---------------- warp-mma GEMM: C[M,N] = sum_k A[m,k]*B[n,k]  (bf16x3 split) --
// 4 warps (128 threads), warp tile 64x64, CTA tile 128x128, 2-stage, 2-sync.
// Inner loop is term-major per A-row-block: each accumulator is revisited only
// every 8 MMAs, eliminating 3-deep HMMA RAW chains. Per-acc summation order is
// unchanged (hh, hl, lh per k-step) => results bitwise identical to R13.
// mode 0: out = acc + bias -> split to (outH, outL) bf16 planes
// else  : out = acc * scale -> outF fp32
__global__ __launch_bounds__(128)
void gemm_mma(const __nv_bfloat16* __restrict__ Ah, const __nv_bfloat16* __restrict__ Al,
              const __nv_bfloat16* __restrict__ Bh, const __nv_bfloat16* __restrict__ Bl,
              const float* __restrict__ bias,
              float* __restrict__ outF,
              __nv_bfloat16* __restrict__ outH, __nv_bfloat16* __restrict__ outL,
              int M, int N, int K, float scale, int mode,
              long long sA, long long sB, long long sC, long long sBias)
{
    extern __shared__ __nv_bfloat16 smem[];

    const int tid = threadIdx.x;
    const long long z = blockIdx.z;
    Ah += z * sA;  Al += z * sA;
    Bh += z * sB;  Bl += z * sB;
    if (bias) bias += z * sBias;
    if (outF) outF += z * sC;
    if (outH) { outH += z * sC; outL += z * sC; }

    const int m0 = blockIdx.y * 128;
    const int n0 = blockIdx.x * 128;

    const int wid = tid >> 5;
    const int wm  = wid & 1;         // 0..1 -> 64-row slice of A
    const int wn  = wid >> 1;        // 0..1 -> 64-col slice of B

    // loader: per plane 128 rows x 4 x 16B; thread covers 4 rows x 1 chunk
    const int rowb = tid >> 2;             // 0..31
    const int jj   = (tid & 3) * 8;        // k offset (elements)
    const uint32_t sb0 = s2u(smem);

    const __nv_bfloat16* gsrc[4] = { Ah, Al, Bh, Bl };
    const int rbase[4] = { m0, m0, n0, n0 };

    // ldmatrix lane offsets (bytes, relative to tile origin within a plane)
    const int l = tid & 31;
    const uint32_t aLaneOff = (uint32_t)(((l & 15) * RS + ((l >> 4) << 3)) * 2);
    const uint32_t bLaneOff = (uint32_t)((((l & 7) + ((l >> 4) << 3)) * RS + (((l >> 3) & 1) << 3)) * 2);

    float acc[4][8][4];
    #pragma unroll
    for (int i = 0; i < 4; i++)
        #pragma unroll
        for (int j = 0; j < 8; j++)
            #pragma unroll
            for (int c = 0; c < 4; c++) acc[i][j][c] = 0.0f;

    const int nchunk = K / KC;

    // prologue: chunks 0 and 1
    #pragma unroll
    for (int c0 = 0; c0 < NSTAGE; c0++) {
        const uint32_t st = sb0 + c0 * STAGE_E * 2;
        #pragma unroll
        for (int pl = 0; pl < 4; pl++) {
            #pragma unroll
            for (int h = 0; h < 4; h++) {
                const int r = rowb + h * 32;
                cpasync16(st + (pl * PLANE_E + r * RS + jj) * 2,
                          gsrc[pl] + (long long)(rbase[pl] + r) * K + c0 * KC + jj);
            }
        }
        cp_commit();
    }

    for (int ic = 0; ic < nchunk; ic++) {
        const int p = ic & 1;
        if (ic + 1 < nchunk) cp_wait1(); else cp_wait0();
        __syncthreads();

        const uint32_t sbase = sb0 + p * STAGE_E * 2;
        const uint32_t aBaseH = sbase + (0 * PLANE_E + (wm * 64) * RS) * 2 + aLaneOff;
        const uint32_t aBaseL = sbase + (1 * PLANE_E + (wm * 64) * RS) * 2 + aLaneOff;
        const uint32_t bBaseH = sbase + (2 * PLANE_E + (wn * 64) * RS) * 2 + bLaneOff;
        const uint32_t bBaseL = sbase + (3 * PLANE_E + (wn * 64) * RS) * 2 + bLaneOff;

        #pragma unroll
        for (int ks = 0; ks < KC / 16; ks++) {
            const uint32_t ko = ks * 32;   // 16 elements * 2 bytes
            uint32_t bh[4][4], bl[4][4];
            #pragma unroll
            for (int jp = 0; jp < 4; jp++) {
                ldsm4(bh[jp], bBaseH + (uint32_t)(jp * 16 * RS * 2) + ko);
                ldsm4(bl[jp], bBaseL + (uint32_t)(jp * 16 * RS * 2) + ko);
            }
            #pragma unroll
            for (int i = 0; i < 4; i++) {
                uint32_t ah[4], al[4];
                ldsm4(ah, aBaseH + (uint32_t)(i * 16 * RS * 2) + ko);
                ldsm4(al, aBaseL + (uint32_t)(i * 16 * RS * 2) + ko);
                // term-major: 8 independent accs per pass, no RAW chains
                #pragma unroll
                for (int jp = 0; jp < 4; jp++)
                    #pragma unroll
                    for (int j2 = 0; j2 < 2; j2++)
                        mma16816(acc[i][jp * 2 + j2], ah, &bh[jp][j2 * 2]);
                #pragma unroll
                for (int jp = 0; jp < 4; jp++)
                    #pragma unroll
                    for (int j2 = 0; j2 < 2; j2++)
                        mma16816(acc[i][jp * 2 + j2], ah, &bl[jp][j2 * 2]);
                #pragma unroll
                for (int jp = 0; jp < 4; jp++)
                    #pragma unroll
                    for (int j2 = 0; j2 < 2; j2++)
                        mma16816(acc[i][jp * 2 + j2], al, &bh[jp][j2 * 2]);
            }
        }
        __syncthreads();

        if (ic + 2 < nchunk) {
            const uint32_t stw = sb0 + p * STAGE_E * 2;
            const int k0 = (ic + 2) * KC;
            #pragma unroll
            for (int pl = 0; pl < 4; pl++) {
                #pragma unroll
                for (int h = 0; h < 4; h++) {
                    const int r = rowb + h * 32;
                    cpasync16(stw + (pl * PLANE_E + r * RS + jj) * 2,
                              gsrc[pl] + (long long)(rbase[pl] + r) * K + k0 + jj);
                }
            }
            cp_commit();
        }
    }

    // ---- epilogue
    const int lt = tid & 31;
    const int rr = lt >> 2;
    const int cc = (lt & 3) << 1;
    const int mbase = m0 + wm * 64 + rr;
    const int nbase = n0 + wn * 64 + cc;

    #pragma unroll
    for (int i = 0; i < 4; i++) {
        #pragma unroll
        for (int j = 0; j < 8; j++) {
            const int mr = mbase + i * 16;
            const int nc = nbase + j * 8;
            if (mode == 0) {
                const float b0 = bias[nc], b1 = bias[nc + 1];
                #pragma unroll
                for (int h = 0; h < 2; h++) {
                    const float x0 = acc[i][j][2 * h]     + b0;
                    const float x1 = acc[i][j][2 * h + 1] + b1;
                    __nv_bfloat16 h0 = __float2bfloat16(x0);
                    __nv_bfloat16 h1 = __float2bfloat16(x1);
                    __nv_bfloat16 l0 = __float2bfloat16(x0 - __bfloat162float(h0));
                    __nv_bfloat16 l1 = __float2bfloat16(x1 - __bfloat162float(h1));
                    const long long o = (long long)(mr + 8 * h) * N + nc;
                    *(uint32_t*)(outH + o) = (uint32_t)__bfloat16_as_ushort(h0) |
                                             ((uint32_t)__bfloat16_as_ushort(h1) << 16);
                    *(uint32_t*)(outL + o) = (uint32_t)__bfloat16_as_ushort(l0) |
                                             ((uint32_t)__bfloat16_as_ushort(l1) << 16);
                }
            } else {
                #pragma unroll
                for (int h = 0; h < 2; h++) {
                    float2 v;
                    v.x = acc[i][j][2 * h]     * scale;
                    v.y = acc[i][j][2 * h + 1] * scale;
                    *(float2*)(outF + (long long)(mr + 8 * h) * N + nc) = v;
                }
            }
        }
    }
}

// ---------------- elementwise: fp32 -> bf16 hi/lo split ------------------------
__global__ __launch_bounds__(256)
void k_split(const float* __restrict__ x, __nv_bfloat16* __restrict__ h,
             __nv_bfloat16* __restrict__ l, long long n)
{
    long long i = ((long long)blockIdx.x * blockDim.x + threadIdx.x) * 4;
    if (i >= n) return;
    float4 v = *(const float4*)(x + i);
    __nv_bfloat16 h0 = __float2bfloat16(v.x), h1 = __float2bfloat16(v.y);
    __nv_bfloat16 h2 = __float2bfloat16(v.z), h3 = __float2bfloat16(v.w);
    __nv_bfloat16 l0 = __float2bfloat16(v.x - __bfloat162float(h0));
    __nv_bfloat16 l1 = __float2bfloat16(v.y - __bfloat162float(h1));
    __nv_bfloat16 l2 = __float2bfloat16(v.z - __bfloat162float(h2));
    __nv_bfloat16 l3 = __float2bfloat16(v.w - __bfloat162float(h3));
    uint2 hv, lv;
    hv.x = (uint32_t)__bfloat16_as_ushort(h0) | ((uint32_t)__bfloat16_as_ushort(h1) << 16);
    hv.y = (uint32_t)__bfloat16_as_ushort(h2) | ((uint32_t)__bfloat16_as_ushort(h3) << 16);
    lv.x = (uint32_t)__bfloat16_as_ushort(l0) | ((uint32_t)__bfloat16_as_ushort(l1) << 16);
    lv.y = (uint32_t)__bfloat16_as_ushort(l2) | ((uint32_t)__bfloat16_as_ushort(l3) << 16);
    *(uint2*)(h + i) = hv;
    *(uint2*)(l + i) = lv;
}

// ---------------- pack 3 bias vectors into one stacked buffer ------------------
__global__ __launch_bounds__(1024)
void k_pack_bias(const float* __restrict__ bq, const float* __restrict__ bk,
                 const float* __restrict__ bv, float* __restrict__ dst)
{
    const int i = threadIdx.x;
    dst[i] = bq[i];
    dst[HID + i] = bk[i];
    dst[2 * HID + i] = bv[i];
}

// ---------------- dual-plane bf16 transpose: [z][R][C] -> [z][C][R] ------------
__global__ __launch_bounds__(256)
void k_tr_bf16_2(const __nv_bfloat16* __restrict__ inH, const __nv_bfloat16* __restrict__ inL,
                 __nv_bfloat16* __restrict__ outH, __nv_bfloat16* __restrict__ outL,
                 int R, int C)
{
    __shared__ __nv_bfloat16 th[32][33];
    __shared__ __nv_bfloat16 tl[32][33];
    const int c0 = blockIdx.x * 32, r0 = blockIdx.y * 32;
    const int tx = threadIdx.x, ty = threadIdx.y;
    const long long zb = (long long)blockIdx.z * R * C;
    #pragma unroll
    for (int k = 0; k < 4; k++) {
        const long long idx = zb + (long long)(r0 + ty + k * 8) * C + c0 + tx;
        th[ty + k * 8][tx] = inH[idx];
        tl[ty + k * 8][tx] = inL[idx];
    }
    __syncthreads();
    #pragma unroll
    for (int k = 0; k < 4; k++) {
        const long long o = zb + (long long)(c0 + ty + k * 8) * R + r0 + tx;
        outH[o] = th[tx][ty + k * 8];
        outL[o] = tl[tx][ty + k * 8];
    }
}

// ---------------- softmax pass 1: per-(b,kq) max + inv-sum over S --------------
__global__ __launch_bounds__(256)
void softmax_stats(const float* __restrict__ attn,
                   float* __restrict__ statM, float* __restrict__ statI)
{
    const int c    = threadIdx.x & 63;
    const int lane = threadIdx.x >> 6;
    const int kq   = blockIdx.x * 64 + c;
    const long long base = (long long)blockIdx.y * SEQL * KQL + kq;
    const int CH = SEQL / 4;
    const int s0 = lane * CH;

    float m = -1e30f, lsum = 0.0f;
    for (int s = 0; s < CH; s++) {
        float x = attn[base + (long long)(s0 + s) * KQL];
        float nm = fmaxf(m, x);
        lsum = lsum * __expf(m - nm) + __expf(x - nm);
        m = nm;
    }
    __shared__ float sm[4][64];
    __shared__ float sl[4][64];
    sm[lane][c] = m;
    sl[lane][c] = lsum;
    __syncthreads();
    if (lane == 0) {
        float M = fmaxf(fmaxf(sm[0][c], sm[1][c]), fmaxf(sm[2][c], sm[3][c]));
        float L = sl[0][c] * __expf(sm[0][c] - M) + sl[1][c] * __expf(sm[1][c] - M)
                + sl[2][c] * __expf(sm[2][c] - M) + sl[3][c] * __expf(sm[3][c] - M);
        statM[(long long)blockIdx.y * KQL + kq] = M;
        statI[(long long)blockIdx.y * KQL + kq] = 1.0f / L;
    }
}

// ---------------- softmax pass 2 fused: normalize in place + transpose+split ---
__global__ __launch_bounds__(256)
void k_norm_tr(float* __restrict__ attn,
               const float* __restrict__ statM, const float* __restrict__ statI,
               __nv_bfloat16* __restrict__ h, __nv_bfloat16* __restrict__ l)
{
    __shared__ float t[32][33];
    const int kq0 = blockIdx.x * 32, s0 = blockIdx.y * 32;
    const int tx = threadIdx.x, ty = threadIdx.y;
    float* ip = attn + (long long)blockIdx.z * SEQL * KQL;
    __nv_bfloat16* hp = h + (long long)blockIdx.z * KQL * SEQL;
    __nv_bfloat16* lp = l + (long long)blockIdx.z * KQL * SEQL;

    const float M = statM[(long long)blockIdx.z * KQL + kq0 + tx];
    const float I = statI[(long long)blockIdx.z * KQL + kq0 + tx];

    #pragma unroll
    for (int k = 0; k < 4; k++) {
        const long long idx = (long long)(s0 + ty + k * 8) * KQL + kq0 + tx;
        float p = __expf(ip[idx] - M) * I;
        ip[idx] = p;
        t[ty + k * 8][tx] = p;
    }
    __syncthreads();
    #pragma unroll
    for (int k = 0; k < 4; k++) {
        float x = t[tx][ty + k * 8];
        __nv_bfloat16 hb = __float2bfloat16(x);
        __nv_bfloat16 lb = __float2bfloat16(x - __bfloat162float(hb));
        long long o = (long long)(kq0 + ty + k * 8) * SEQL + s0 + tx;
        hp[o] = hb;
        lp[o] = lb;
    }
}

// ---------------- launch -------------------------------------------------------
extern "C" void kernel_launch(void* const* d_in, const int* in_sizes, int n_in,
                              void* d_out, int out_size)
{
    const float* queries = (const float*)d_in[0];
    const float* keys    = (const float*)d_in[1];
    const float* values  = (const float*)d_in[2];
    const float* Wq      = (const float*)d_in[3];
    const float* bq      = (const float*)d_in[4];
    const float* Wk      = (const float*)d_in[5];
    const float* bk      = (const float*)d_in[6];
    const float* Wv      = (const float*)d_in[7];
    const float* bv      = (const float*)d_in[8];

    float* ctx  = (float*)d_out;
    float* attn = (float*)d_out + NT;

    __nv_bfloat16 *xh, *xl, *wh, *wl, *qkvh, *qkvl, *vth, *vtl, *ath, *atl;
    float *bias, *statM, *statI;
    cudaGetSymbolAddress((void**)&xh, g_xh);     cudaGetSymbolAddress((void**)&xl, g_xl);
    cudaGetSymbolAddress((void**)&wh, g_wh);     cudaGetSymbolAddress((void**)&wl, g_wl);
    cudaGetSymbolAddress((void**)&qkvh, g_qkvh); cudaGetSymbolAddress((void**)&qkvl, g_qkvl);
    cudaGetSymbolAddress((void**)&vth, g_vth);   cudaGetSymbolAddress((void**)&vtl, g_vtl);
    cudaGetSymbolAddress((void**)&ath, g_ath);   cudaGetSymbolAddress((void**)&atl, g_atl);
    cudaGetSymbolAddress((void**)&bias, g_bias);
    cudaGetSymbolAddress((void**)&statM, g_statM);
    cudaGetSymbolAddress((void**)&statI, g_statI);

    cudaFuncSetAttribute(gemm_mma, cudaFuncAttributeMaxDynamicSharedMemorySize, GEMM_SMEM);

    dim3 b256(256);
    dim3 b128(128);
    dim3 trb(32, 8);

    // ---- convert inputs + weights to stacked bf16 hi/lo planes
    k_split<<<(unsigned)(NT / 1024), b256>>>(queries, xh,          xl,          NT);
    k_split<<<(unsigned)(NT / 1024), b256>>>(keys,    xh + NT,     xl + NT,     NT);
    k_split<<<(unsigned)(NT / 1024), b256>>>(values,  xh + 2 * NT, xl + 2 * NT, NT);
    k_split<<<(unsigned)(NW / 1024), b256>>>(Wq, wh,          wl,          NW);
    k_split<<<(unsigned)(NW / 1024), b256>>>(Wk, wh + NW,     wl + NW,     NW);
    k_split<<<(unsigned)(NW / 1024), b256>>>(Wv, wh + 2 * NW, wl + 2 * NW, NW);
    k_pack_bias<<<1, 1024>>>(bq, bk, bv, bias);

    // ---- merged Q/K/V projection (z = 0,1,2)
    gemm_mma<<<dim3(HID / 128, (BATCH * KQL) / 128, 3), b128, GEMM_SMEM>>>(
        xh, xl, wh, wl, bias, nullptr, qkvh, qkvl,
        BATCH * KQL, HID, HID, 1.0f, 0,
        (long long)NT, (long long)NW, (long long)NT, (long long)HID);

    const __nv_bfloat16* qh = qkvh;              const __nv_bfloat16* ql = qkvl;
    const __nv_bfloat16* kh = qkvh + NT;         const __nv_bfloat16* kl = qkvl + NT;
    const __nv_bfloat16* vh = qkvh + 2 * NT;     const __nv_bfloat16* vl = qkvl + 2 * NT;

    // ---- v transpose [b][s][h] -> [b][h][s] (both planes, one launch)
    k_tr_bf16_2<<<dim3(HID / 32, SEQL / 32, BATCH), trb>>>(vh, vl, vth, vtl, SEQL, HID);

    // ---- scores[b][s][kq] = (k . q) / 32, straight into d_out attn
    gemm_mma<<<dim3(KQL / 128, SEQL / 128, BATCH), b128, GEMM_SMEM>>>(
        kh, kl, qh, ql, nullptr, attn, nullptr, nullptr,
        SEQL, KQL, HID, 0.03125f, 1,
        (long long)SEQL * HID, (long long)KQL * HID, (long long)SEQL * KQL, 0);

    // ---- softmax stats, then fused normalize + transpose + split
    softmax_stats<<<dim3(KQL / 64, BATCH), b256>>>(attn, statM, statI);
    k_norm_tr<<<dim3(KQL / 32, SEQL / 32, BATCH), trb>>>(attn, statM, statI, ath, atl);

    // ---- context[b][kq][h] = sum_s attnT[kq][s] * vT[h][s]
    gemm_mma<<<dim3(HID / 128, KQL / 128, BATCH), b128, GEMM_SMEM>>>(
        ath, atl, vth, vtl, nullptr, ctx, nullptr, nullptr,
        KQL, HID, SEQL, 1.0f, 2,
        (long long)KQL * SEQL, (long long)HID * SEQL, (long long)KQL * HID, 0);
}

// round 16
// speedup vs baseline: 1.5193x; 1.5193x over previous
#include <cuda_runtime.h>
#include <cuda_bf16.h>
#include <stdint.h>
#include <math.h>

#define BATCH 4
#define SEQL  4096
#define KQL   4096
#define HID   1024
#define NT    ((size_t)BATCH * KQL * HID)   // 16,777,216 els per qkv plane
#define NW    ((size_t)HID * HID)           // 1,048,576 els per weight

// ---------------- device scratch (allocation-free rule: __device__ globals) ----
__device__ __nv_bfloat16 g_xh[3 * NT];      // stacked inputs (q,k,v) hi
__device__ __nv_bfloat16 g_xl[3 * NT];
__device__ __nv_bfloat16 g_wh[3 * NW];      // stacked weights hi
__device__ __nv_bfloat16 g_wl[3 * NW];
__device__ float         g_bias[3 * HID];   // stacked biases
__device__ __nv_bfloat16 g_qkvh[3 * NT];    // stacked projected q,k,v hi
__device__ __nv_bfloat16 g_qkvl[3 * NT];
__device__ __nv_bfloat16 g_vth[(size_t)BATCH * HID * SEQL];
__device__ __nv_bfloat16 g_vtl[(size_t)BATCH * HID * SEQL];
__device__ __nv_bfloat16 g_ath[(size_t)BATCH * KQL * SEQL];
__device__ __nv_bfloat16 g_atl[(size_t)BATCH * KQL * SEQL];
__device__ float         g_statM[(size_t)BATCH * KQL];
__device__ float         g_statI[(size_t)BATCH * KQL];

// ---------------- helpers ------------------------------------------------------
__device__ __forceinline__ uint32_t s2u(const void* p) {
    return (uint32_t)__cvta_generic_to_shared(p);
}
__device__ __forceinline__ void cpasync16(uint32_t dst, const void* src) {
    asm volatile("cp.async.cg.shared.global [%0], [%1], 16;" :: "r"(dst), "l"(src));
}
__device__ __forceinline__ void cp_commit() {
    asm volatile("cp.async.commit_group;" ::: "memory");
}
__device__ __forceinline__ void cp_wait1() {
    asm volatile("cp.async.wait_group 1;" ::: "memory");
}
__device__ __forceinline__ void cp_wait0() {
    asm volatile("cp.async.wait_group 0;" ::: "memory");
}
// D += A * B  (m16n8k16, row.col, bf16 in / f32 accum)
__device__ __forceinline__ void mma16816(float c[4], const uint32_t a[4], const uint32_t* b) {
    asm volatile(
        "mma.sync.aligned.m16n8k16.row.col.f32.bf16.bf16.f32 "
        "{%0,%1,%2,%3}, {%4,%5,%6,%7}, {%8,%9}, {%0,%1,%2,%3};"
        : "+f"(c[0]), "+f"(c[1]), "+f"(c[2]), "+f"(c[3])
        : "r"(a[0]), "r"(a[1]), "r"(a[2]), "r"(a[3]), "r"(b[0]), "r"(b[1]));
}
__device__ __forceinline__ void ldsm4(uint32_t r[4], uint32_t saddr) {
    asm volatile("ldmatrix.sync.aligned.m8n8.x4.shared.b16 {%0,%1,%2,%3}, [%4];"
                 : "=r"(r[0]), "=r"(r[1]), "=r"(r[2]), "=r"(r[3]) : "r"(saddr));
}

// smem geometry: 4 planes (Ah, Al, Bh, Bl), each 128 rows x KC bf16, padded
#define KC      32
#define RS      40                    // padded row stride in bf16 (80B)
#define PLANE_E (128 * RS)
#define STAGE_E (4 * PLANE_E)
#define NSTAGE  2
#define GEMM_SMEM (NSTAGE * STAGE_E * 2)   // 81920 bytes -> 2 CTAs/SM

// ---------------- warp-mma GEMM: C[M,N] = sum_k A[m,k]*B[n,k]  (bf16x3 split) --
// 4 warps (128 threads), warp tile 64x64, CTA tile 128x128, 2-stage, 2-sync.
// Inner loop: within each jp the two j2 accumulators alternate, doubling the
// same-acc reuse distance without any extra live registers. Per-acc summation
// order unchanged (hh, hl, lh per k-step) => bitwise identical results.
// mode 0: out = acc + bias -> split to (outH, outL) bf16 planes
// else  : out = acc * scale -> outF fp32
__global__ __launch_bounds__(128)
void gemm_mma(const __nv_bfloat16* __restrict__ Ah, const __nv_bfloat16* __restrict__ Al,
              const __nv_bfloat16* __restrict__ Bh, const __nv_bfloat16* __restrict__ Bl,
              const float* __restrict__ bias,
              float* __restrict__ outF,
              __nv_bfloat16* __restrict__ outH, __nv_bfloat16* __restrict__ outL,
              int M, int N, int K, float scale, int mode,
              long long sA, long long sB, long long sC, long long sBias)
{
    extern __shared__ __nv_bfloat16 smem[];

    const int tid = threadIdx.x;
    const long long z = blockIdx.z;
    Ah += z * sA;  Al += z * sA;
    Bh += z * sB;  Bl += z * sB;
    if (bias) bias += z * sBias;
    if (outF) outF += z * sC;
    if (outH) { outH += z * sC; outL += z * sC; }

    const int m0 = blockIdx.y * 128;
    const int n0 = blockIdx.x * 128;

    const int wid = tid >> 5;
    const int wm  = wid & 1;         // 0..1 -> 64-row slice of A
    const int wn  = wid >> 1;        // 0..1 -> 64-col slice of B

    // loader: per plane 128 rows x 4 x 16B; thread covers 4 rows x 1 chunk
    const int rowb = tid >> 2;             // 0..31
    const int jj   = (tid & 3) * 8;        // k offset (elements)
    const uint32_t sb0 = s2u(smem);

    const __nv_bfloat16* gsrc[4] = { Ah, Al, Bh, Bl };
    const int rbase[4] = { m0, m0, n0, n0 };

    // ldmatrix lane offsets (bytes, relative to tile origin within a plane)
    const int l = tid & 31;
    const uint32_t aLaneOff = (uint32_t)(((l & 15) * RS + ((l >> 4) << 3)) * 2);
    const uint32_t bLaneOff = (uint32_t)((((l & 7) + ((l >> 4) << 3)) * RS + (((l >> 3) & 1) << 3)) * 2);

    float acc[4][8][4];
    #pragma unroll
    for (int i = 0; i < 4; i++)
        #pragma unroll
        for (int j = 0; j < 8; j++)
            #pragma unroll
            for (int c = 0; c < 4; c++) acc[i][j][c] = 0.0f;

    const int nchunk = K / KC;

    // prologue: chunks 0 and 1
    #pragma unroll
    for (int c0 = 0; c0 < NSTAGE; c0++) {
        const uint32_t st = sb0 + c0 * STAGE_E * 2;
        #pragma unroll
        for (int pl = 0; pl < 4; pl++) {
            #pragma unroll
            for (int h = 0; h < 4; h++) {
                const int r = rowb + h * 32;
                cpasync16(st + (pl * PLANE_E + r * RS + jj) * 2,
                          gsrc[pl] + (long long)(rbase[pl] + r) * K + c0 * KC + jj);
            }
        }
        cp_commit();
    }

    for (int ic = 0; ic < nchunk; ic++) {
        const int p = ic & 1;
        if (ic + 1 < nchunk) cp_wait1(); else cp_wait0();
        __syncthreads();

        const uint32_t sbase = sb0 + p * STAGE_E * 2;
        const uint32_t aBaseH = sbase + (0 * PLANE_E + (wm * 64) * RS) * 2 + aLaneOff;
        const uint32_t aBaseL = sbase + (1 * PLANE_E + (wm * 64) * RS) * 2 + aLaneOff;
        const uint32_t bBaseH = sbase + (2 * PLANE_E + (wn * 64) * RS) * 2 + bLaneOff;
        const uint32_t bBaseL = sbase + (3 * PLANE_E + (wn * 64) * RS) * 2 + bLaneOff;

        #pragma unroll
        for (int ks = 0; ks < KC / 16; ks++) {
            const uint32_t ko = ks * 32;   // 16 elements * 2 bytes
            uint32_t bh[4][4], bl[4][4];
            #pragma unroll
            for (int jp = 0; jp < 4; jp++) {
                ldsm4(bh[jp], bBaseH + (uint32_t)(jp * 16 * RS * 2) + ko);
                ldsm4(bl[jp], bBaseL + (uint32_t)(jp * 16 * RS * 2) + ko);
            }
            #pragma unroll
            for (int i = 0; i < 4; i++) {
                uint32_t ah[4], al[4];
                ldsm4(ah, aBaseH + (uint32_t)(i * 16 * RS * 2) + ko);
                ldsm4(al, aBaseL + (uint32_t)(i * 16 * RS * 2) + ko);
                #pragma unroll
                for (int jp = 0; jp < 4; jp++) {
                    // alternate the two j2 accumulators: reuse distance 2,
                    // per-acc order still hh -> hl -> lh
                    mma16816(acc[i][jp * 2 + 0], ah, &bh[jp][0]);
                    mma16816(acc[i][jp * 2 + 1], ah, &bh[jp][2]);
                    mma16816(acc[i][jp * 2 + 0], ah, &bl[jp][0]);
                    mma16816(acc[i][jp * 2 + 1], ah, &bl[jp][2]);
                    mma16816(acc[i][jp * 2 + 0], al, &bh[jp][0]);
                    mma16816(acc[i][jp * 2 + 1], al, &bh[jp][2]);
                }
            }
        }
        __syncthreads();

        if (ic + 2 < nchunk) {
            const uint32_t stw = sb0 + p * STAGE_E * 2;
            const int k0 = (ic + 2) * KC;
            #pragma unroll
            for (int pl = 0; pl < 4; pl++) {
                #pragma unroll
                for (int h = 0; h < 4; h++) {
                    const int r = rowb + h * 32;
                    cpasync16(stw + (pl * PLANE_E + r * RS + jj) * 2,
                              gsrc[pl] + (long long)(rbase[pl] + r) * K + k0 + jj);
                }
            }
            cp_commit();
        }
    }

    // ---- epilogue
    const int lt = tid & 31;
    const int rr = lt >> 2;
    const int cc = (lt & 3) << 1;
    const int mbase = m0 + wm * 64 + rr;
    const int nbase = n0 + wn * 64 + cc;

    #pragma unroll
    for (int i = 0; i < 4; i++) {
        #pragma unroll
        for (int j = 0; j < 8; j++) {
            const int mr = mbase + i * 16;
            const int nc = nbase + j * 8;
            if (mode == 0) {
                const float b0 = bias[nc], b1 = bias[nc + 1];
                #pragma unroll
                for (int h = 0; h < 2; h++) {
                    const float x0 = acc[i][j][2 * h]     + b0;
                    const float x1 = acc[i][j][2 * h + 1] + b1;
                    __nv_bfloat16 h0 = __float2bfloat16(x0);
                    __nv_bfloat16 h1 = __float2bfloat16(x1);
                    __nv_bfloat16 l0 = __float2bfloat16(x0 - __bfloat162float(h0));
                    __nv_bfloat16 l1 = __float2bfloat16(x1 - __bfloat162float(h1));
                    const long long o = (long long)(mr + 8 * h) * N + nc;
                    *(uint32_t*)(outH + o) = (uint32_t)__bfloat16_as_ushort(h0) |
                                             ((uint32_t)__bfloat16_as_ushort(h1) << 16);
                    *(uint32_t*)(outL + o) = (uint32_t)__bfloat16_as_ushort(l0) |
                                             ((uint32_t)__bfloat16_as_ushort(l1) << 16);
                }
            } else {
                #pragma unroll
                for (int h = 0; h < 2; h++) {
                    float2 v;
                    v.x = acc[i][j][2 * h]     * scale;
                    v.y = acc[i][j][2 * h + 1] * scale;
                    *(float2*)(outF + (long long)(mr + 8 * h) * N + nc) = v;
                }
            }
        }
    }
}

// ---------------- elementwise: fp32 -> bf16 hi/lo split ------------------------
__global__ __launch_bounds__(256)
void k_split(const float* __restrict__ x, __nv_bfloat16* __restrict__ h,
             __nv_bfloat16* __restrict__ l, long long n)
{
    long long i = ((long long)blockIdx.x * blockDim.x + threadIdx.x) * 4;
    if (i >= n) return;
    float4 v = *(const float4*)(x + i);
    __nv_bfloat16 h0 = __float2bfloat16(v.x), h1 = __float2bfloat16(v.y);
    __nv_bfloat16 h2 = __float2bfloat16(v.z), h3 = __float2bfloat16(v.w);
    __nv_bfloat16 l0 = __float2bfloat16(v.x - __bfloat162float(h0));
    __nv_bfloat16 l1 = __float2bfloat16(v.y - __bfloat162float(h1));
    __nv_bfloat16 l2 = __float2bfloat16(v.z - __bfloat162float(h2));
    __nv_bfloat16 l3 = __float2bfloat16(v.w - __bfloat162float(h3));
    uint2 hv, lv;
    hv.x = (uint32_t)__bfloat16_as_ushort(h0) | ((uint32_t)__bfloat16_as_ushort(h1) << 16);
    hv.y = (uint32_t)__bfloat16_as_ushort(h2) | ((uint32_t)__bfloat16_as_ushort(h3) << 16);
    lv.x = (uint32_t)__bfloat16_as_ushort(l0) | ((uint32_t)__bfloat16_as_ushort(l1) << 16);
    lv.y = (uint32_t)__bfloat16_as_ushort(l2) | ((uint32_t)__bfloat16_as_ushort(l3) << 16);
    *(uint2*)(h + i) = hv;
    *(uint2*)(l + i) = lv;
}

// ---------------- pack 3 bias vectors into one stacked buffer ------------------
__global__ __launch_bounds__(1024)
void k_pack_bias(const float* __restrict__ bq, const float* __restrict__ bk,
                 const float* __restrict__ bv, float* __restrict__ dst)
{
    const int i = threadIdx.x;
    dst[i] = bq[i];
    dst[HID + i] = bk[i];
    dst[2 * HID + i] = bv[i];
}

// ---------------- dual-plane bf16 transpose: [z][R][C] -> [z][C][R] ------------
__global__ __launch_bounds__(256)
void k_tr_bf16_2(const __nv_bfloat16* __restrict__ inH, const __nv_bfloat16* __restrict__ inL,
                 __nv_bfloat16* __restrict__ outH, __nv_bfloat16* __restrict__ outL,
                 int R, int C)
{
    __shared__ __nv_bfloat16 th[32][33];
    __shared__ __nv_bfloat16 tl[32][33];
    const int c0 = blockIdx.x * 32, r0 = blockIdx.y * 32;
    const int tx = threadIdx.x, ty = threadIdx.y;
    const long long zb = (long long)blockIdx.z * R * C;
    #pragma unroll
    for (int k = 0; k < 4; k++) {
        const long long idx = zb + (long long)(r0 + ty + k * 8) * C + c0 + tx;
        th[ty + k * 8][tx] = inH[idx];
        tl[ty + k * 8][tx] = inL[idx];
    }
    __syncthreads();
    #pragma unroll
    for (int k = 0; k < 4; k++) {
        const long long o = zb + (long long)(c0 + ty + k * 8) * R + r0 + tx;
        outH[o] = th[tx][ty + k * 8];
        outL[o] = tl[tx][ty + k * 8];
    }
}

// ---------------- softmax pass 1: per-(b,kq) max + inv-sum over S --------------
__global__ __launch_bounds__(256)
void softmax_stats(const float* __restrict__ attn,
                   float* __restrict__ statM, float* __restrict__ statI)
{
    const int c    = threadIdx.x & 63;
    const int lane = threadIdx.x >> 6;
    const int kq   = blockIdx.x * 64 + c;
    const long long base = (long long)blockIdx.y * SEQL * KQL + kq;
    const int CH = SEQL / 4;
    const int s0 = lane * CH;

    float m = -1e30f, lsum = 0.0f;
    for (int s = 0; s < CH; s++) {
        float x = attn[base + (long long)(s0 + s) * KQL];
        float nm = fmaxf(m, x);
        lsum = lsum * __expf(m - nm) + __expf(x - nm);
        m = nm;
    }
    __shared__ float sm[4][64];
    __shared__ float sl[4][64];
    sm[lane][c] = m;
    sl[lane][c] = lsum;
    __syncthreads();
    if (lane == 0) {
        float M = fmaxf(fmaxf(sm[0][c], sm[1][c]), fmaxf(sm[2][c], sm[3][c]));
        float L = sl[0][c] * __expf(sm[0][c] - M) + sl[1][c] * __expf(sm[1][c] - M)
                + sl[2][c] * __expf(sm[2][c] - M) + sl[3][c] * __expf(sm[3][c] - M);
        statM[(long long)blockIdx.y * KQL + kq] = M;
        statI[(long long)blockIdx.y * KQL + kq] = 1.0f / L;
    }
}

// ---------------- softmax pass 2 fused: normalize in place + transpose+split ---
__global__ __launch_bounds__(256)
void k_norm_tr(float* __restrict__ attn,
               const float* __restrict__ statM, const float* __restrict__ statI,
               __nv_bfloat16* __restrict__ h, __nv_bfloat16* __restrict__ l)
{
    __shared__ float t[32][33];
    const int kq0 = blockIdx.x * 32, s0 = blockIdx.y * 32;
    const int tx = threadIdx.x, ty = threadIdx.y;
    float* ip = attn + (long long)blockIdx.z * SEQL * KQL;
    __nv_bfloat16* hp = h + (long long)blockIdx.z * KQL * SEQL;
    __nv_bfloat16* lp = l + (long long)blockIdx.z * KQL * SEQL;

    const float M = statM[(long long)blockIdx.z * KQL + kq0 + tx];
    const float I = statI[(long long)blockIdx.z * KQL + kq0 + tx];

    #pragma unroll
    for (int k = 0; k < 4; k++) {
        const long long idx = (long long)(s0 + ty + k * 8) * KQL + kq0 + tx;
        float p = __expf(ip[idx] - M) * I;
        ip[idx] = p;
        t[ty + k * 8][tx] = p;
    }
    __syncthreads();
    #pragma unroll
    for (int k = 0; k < 4; k++) {
        float x = t[tx][ty + k * 8];
        __nv_bfloat16 hb = __float2bfloat16(x);
        __nv_bfloat16 lb = __float2bfloat16(x - __bfloat162float(hb));
        long long o = (long long)(kq0 + ty + k * 8) * SEQL + s0 + tx;
        hp[o] = hb;
        lp[o] = lb;
    }
}

// ---------------- launch -------------------------------------------------------
extern "C" void kernel_launch(void* const* d_in, const int* in_sizes, int n_in,
                              void* d_out, int out_size)
{
    const float* queries = (const float*)d_in[0];
    const float* keys    = (const float*)d_in[1];
    const float* values  = (const float*)d_in[2];
    const float* Wq      = (const float*)d_in[3];
    const float* bq      = (const float*)d_in[4];
    const float* Wk      = (const float*)d_in[5];
    const float* bk      = (const float*)d_in[6];
    const float* Wv      = (const float*)d_in[7];
    const float* bv      = (const float*)d_in[8];

    float* ctx  = (float*)d_out;
    float* attn = (float*)d_out + NT;

    __nv_bfloat16 *xh, *xl, *wh, *wl, *qkvh, *qkvl, *vth, *vtl, *ath, *atl;
    float *bias, *statM, *statI;
    cudaGetSymbolAddress((void**)&xh, g_xh);     cudaGetSymbolAddress((void**)&xl, g_xl);
    cudaGetSymbolAddress((void**)&wh, g_wh);     cudaGetSymbolAddress((void**)&wl, g_wl);
    cudaGetSymbolAddress((void**)&qkvh, g_qkvh); cudaGetSymbolAddress((void**)&qkvl, g_qkvl);
    cudaGetSymbolAddress((void**)&vth, g_vth);   cudaGetSymbolAddress((void**)&vtl, g_vtl);
    cudaGetSymbolAddress((void**)&ath, g_ath);   cudaGetSymbolAddress((void**)&atl, g_atl);
    cudaGetSymbolAddress((void**)&bias, g_bias);
    cudaGetSymbolAddress((void**)&statM, g_statM);
    cudaGetSymbolAddress((void**)&statI, g_statI);

    cudaFuncSetAttribute(gemm_mma, cudaFuncAttributeMaxDynamicSharedMemorySize, GEMM_SMEM);

    dim3 b256(256);
    dim3 b128(128);
    dim3 trb(32, 8);

    // ---- convert inputs + weights to stacked bf16 hi/lo planes
    k_split<<<(unsigned)(NT / 1024), b256>>>(queries, xh,          xl,          NT);
    k_split<<<(unsigned)(NT / 1024), b256>>>(keys,    xh + NT,     xl + NT,     NT);
    k_split<<<(unsigned)(NT / 1024), b256>>>(values,  xh + 2 * NT, xl + 2 * NT, NT);
    k_split<<<(unsigned)(NW / 1024), b256>>>(Wq, wh,          wl,          NW);
    k_split<<<(unsigned)(NW / 1024), b256>>>(Wk, wh + NW,     wl + NW,     NW);
    k_split<<<(unsigned)(NW / 1024), b256>>>(Wv, wh + 2 * NW, wl + 2 * NW, NW);
    k_pack_bias<<<1, 1024>>>(bq, bk, bv, bias);

    // ---- merged Q/K/V projection (z = 0,1,2)
    gemm_mma<<<dim3(HID / 128, (BATCH * KQL) / 128, 3), b128, GEMM_SMEM>>>(
        xh, xl, wh, wl, bias, nullptr, qkvh, qkvl,
        BATCH * KQL, HID, HID, 1.0f, 0,
        (long long)NT, (long long)NW, (long long)NT, (long long)HID);

    const __nv_bfloat16* qh = qkvh;              const __nv_bfloat16* ql = qkvl;
    const __nv_bfloat16* kh = qkvh + NT;         const __nv_bfloat16* kl = qkvl + NT;
    const __nv_bfloat16* vh = qkvh + 2 * NT;     const __nv_bfloat16* vl = qkvl + 2 * NT;

    // ---- v transpose [b][s][h] -> [b][h][s] (both planes, one launch)
    k_tr_bf16_2<<<dim3(HID / 32, SEQL / 32, BATCH), trb>>>(vh, vl, vth, vtl, SEQL, HID);

    // ---- scores[b][s][kq] = (k . q) / 32, straight into d_out attn
    gemm_mma<<<dim3(KQL / 128, SEQL / 128, BATCH), b128, GEMM_SMEM>>>(
        kh, kl, qh, ql, nullptr, attn, nullptr, nullptr,
        SEQL, KQL, HID, 0.03125f, 1,
        (long long)SEQL * HID, (long long)KQL * HID, (long long)SEQL * KQL, 0);

    // ---- softmax stats, then fused normalize + transpose + split
    softmax_stats<<<dim3(KQL / 64, BATCH), b256>>>(attn, statM, statI);
    k_norm_tr<<<dim3(KQL / 32, SEQL / 32, BATCH), trb>>>(attn, statM, statI, ath, atl);

    // ---- context[b][kq][h] = sum_s attnT[kq][s] * vT[h][s]
    gemm_mma<<<dim3(HID / 128, KQL / 128, BATCH), b128, GEMM_SMEM>>>(
        ath, atl, vth, vtl, nullptr, ctx, nullptr, nullptr,
        KQL, HID, SEQL, 1.0f, 2,
        (long long)KQL * SEQL, (long long)HID * SEQL, (long long)KQL * HID, 0);
}

// round 17
// speedup vs baseline: 1.5233x; 1.0026x over previous
#include <cuda_runtime.h>
#include <cuda_fp16.h>
#include <stdint.h>
#include <math.h>

#define BATCH 4
#define SEQL  4096
#define KQL   4096
#define HID   1024
#define NT    ((size_t)BATCH * KQL * HID)   // 16,777,216 els per qkv plane
#define NW    ((size_t)HID * HID)           // 1,048,576 els per weight

// ---------------- device scratch (allocation-free rule: __device__ globals) ----
__device__ __half g_xh[3 * NT];      // stacked inputs (q,k,v) hi
__device__ __half g_xl[3 * NT];
__device__ __half g_wh[3 * NW];      // stacked weights hi
__device__ __half g_wl[3 * NW];
__device__ float  g_bias[3 * HID];   // stacked biases
__device__ __half g_qkvh[3 * NT];    // stacked projected q,k,v hi
__device__ __half g_qkvl[3 * NT];
__device__ __half g_vth[(size_t)BATCH * HID * SEQL];
__device__ __half g_vtl[(size_t)BATCH * HID * SEQL];
__device__ __half g_ath[(size_t)BATCH * KQL * SEQL];   // attn hi only (2-term ctx)
__device__ float  g_statM[(size_t)BATCH * KQL];
__device__ float  g_statI[(size_t)BATCH * KQL];

// ---------------- helpers ------------------------------------------------------
__device__ __forceinline__ uint32_t s2u(const void* p) {
    return (uint32_t)__cvta_generic_to_shared(p);
}
__device__ __forceinline__ void cpasync16(uint32_t dst, const void* src) {
    asm volatile("cp.async.cg.shared.global [%0], [%1], 16;" :: "r"(dst), "l"(src));
}
__device__ __forceinline__ void cp_commit() {
    asm volatile("cp.async.commit_group;" ::: "memory");
}
__device__ __forceinline__ void cp_wait1() {
    asm volatile("cp.async.wait_group 1;" ::: "memory");
}
__device__ __forceinline__ void cp_wait0() {
    asm volatile("cp.async.wait_group 0;" ::: "memory");
}
// D += A * B  (m16n8k16, row.col, fp16 in / f32 accum)
__device__ __forceinline__ void mma16816(float c[4], const uint32_t a[4], const uint32_t* b) {
    asm volatile(
        "mma.sync.aligned.m16n8k16.row.col.f32.f16.f16.f32 "
        "{%0,%1,%2,%3}, {%4,%5,%6,%7}, {%8,%9}, {%0,%1,%2,%3};"
        : "+f"(c[0]), "+f"(c[1]), "+f"(c[2]), "+f"(c[3])
        : "r"(a[0]), "r"(a[1]), "r"(a[2]), "r"(a[3]), "r"(b[0]), "r"(b[1]));
}
__device__ __forceinline__ void ldsm4(uint32_t r[4], uint32_t saddr) {
    asm volatile("ldmatrix.sync.aligned.m8n8.x4.shared.b16 {%0,%1,%2,%3}, [%4];"
                 : "=r"(r[0]), "=r"(r[1]), "=r"(r[2]), "=r"(r[3]) : "r"(saddr));
}

// smem geometry: 4 planes (Ah, Al, Bh, Bl), each 128 rows x KC fp16, padded
#define KC      32
#define RS      40                    // padded row stride in fp16 (80B)
#define PLANE_E (128 * RS)
#define STAGE_E (4 * PLANE_E)
#define NSTAGE  2
#define GEMM_SMEM (NSTAGE * STAGE_E * 2)   // 81920 bytes -> 2 CTAs/SM

// ---------------- warp-mma GEMM: C[M,N] = sum_k A[m,k]*B[n,k]  (fp16 split) ----
// 4 warps (128 threads), warp tile 64x64, CTA tile 128x128, 2-stage, 2-sync.
// terms==3: ah*bh + ah*bl + al*bh (error ~2^-22)
// terms==2: ah*bh + ah*bl          (error ~2^-12; Al plane never loaded)
// mode 0: out = acc + bias -> split to (outH, outL) fp16 planes
// else  : out = acc * scale -> outF fp32
__global__ __launch_bounds__(128)
void gemm_mma(const __half* __restrict__ Ah, const __half* __restrict__ Al,
              const __half* __restrict__ Bh, const __half* __restrict__ Bl,
              const float* __restrict__ bias,
              float* __restrict__ outF,
              __half* __restrict__ outH, __half* __restrict__ outL,
              int M, int N, int K, float scale, int mode, int terms,
              long long sA, long long sB, long long sC, long long sBias)
{
    extern __shared__ __half smem[];

    const int tid = threadIdx.x;
    const long long z = blockIdx.z;
    Ah += z * sA;  if (Al) Al += z * sA;
    Bh += z * sB;  Bl += z * sB;
    if (bias) bias += z * sBias;
    if (outF) outF += z * sC;
    if (outH) { outH += z * sC; outL += z * sC; }

    const int m0 = blockIdx.y * 128;
    const int n0 = blockIdx.x * 128;

    const int wid = tid >> 5;
    const int wm  = wid & 1;         // 0..1 -> 64-row slice of A
    const int wn  = wid >> 1;        // 0..1 -> 64-col slice of B

    // loader: per plane 128 rows x 4 x 16B; thread covers 4 rows x 1 chunk
    const int rowb = tid >> 2;             // 0..31
    const int jj   = (tid & 3) * 8;        // k offset (elements)
    const uint32_t sb0 = s2u(smem);

    const __half* gsrc[4] = { Ah, Al, Bh, Bl };
    const int rbase[4] = { m0, m0, n0, n0 };

    // ldmatrix lane offsets (bytes, relative to tile origin within a plane)
    const int l = tid & 31;
    const uint32_t aLaneOff = (uint32_t)(((l & 15) * RS + ((l >> 4) << 3)) * 2);
    const uint32_t bLaneOff = (uint32_t)((((l & 7) + ((l >> 4) << 3)) * RS + (((l >> 3) & 1) << 3)) * 2);

    float acc[4][8][4];
    #pragma unroll
    for (int i = 0; i < 4; i++)
        #pragma unroll
        for (int j = 0; j < 8; j++)
            #pragma unroll
            for (int c = 0; c < 4; c++) acc[i][j][c] = 0.0f;

    const int nchunk = K / KC;

    // prologue: chunks 0 and 1
    #pragma unroll
    for (int c0 = 0; c0 < NSTAGE; c0++) {
        const uint32_t st = sb0 + c0 * STAGE_E * 2;
        #pragma unroll
        for (int pl = 0; pl < 4; pl++) {
            if (pl == 1 && terms == 2) continue;
            #pragma unroll
            for (int h = 0; h < 4; h++) {
                const int r = rowb + h * 32;
                cpasync16(st + (pl * PLANE_E + r * RS + jj) * 2,
                          gsrc[pl] + (long long)(rbase[pl] + r) * K + c0 * KC + jj);
            }
        }
        cp_commit();
    }

    for (int ic = 0; ic < nchunk; ic++) {
        const int p = ic & 1;
        if (ic + 1 < nchunk) cp_wait1(); else cp_wait0();
        __syncthreads();

        const uint32_t sbase = sb0 + p * STAGE_E * 2;
        const uint32_t aBaseH = sbase + (0 * PLANE_E + (wm * 64) * RS) * 2 + aLaneOff;
        const uint32_t aBaseL = sbase + (1 * PLANE_E + (wm * 64) * RS) * 2 + aLaneOff;
        const uint32_t bBaseH = sbase + (2 * PLANE_E + (wn * 64) * RS) * 2 + bLaneOff;
        const uint32_t bBaseL = sbase + (3 * PLANE_E + (wn * 64) * RS) * 2 + bLaneOff;

        #pragma unroll
        for (int ks = 0; ks < KC / 16; ks++) {
            const uint32_t ko = ks * 32;   // 16 elements * 2 bytes
            uint32_t bh[4][4], bl[4][4];
            #pragma unroll
            for (int jp = 0; jp < 4; jp++) {
                ldsm4(bh[jp], bBaseH + (uint32_t)(jp * 16 * RS * 2) + ko);
                ldsm4(bl[jp], bBaseL + (uint32_t)(jp * 16 * RS * 2) + ko);
            }
            #pragma unroll
            for (int i = 0; i < 4; i++) {
                uint32_t ah[4], al[4];
                ldsm4(ah, aBaseH + (uint32_t)(i * 16 * RS * 2) + ko);
                if (terms == 3)
                    ldsm4(al, aBaseL + (uint32_t)(i * 16 * RS * 2) + ko);
                #pragma unroll
                for (int jp = 0; jp < 4; jp++) {
                    mma16816(acc[i][jp * 2 + 0], ah, &bh[jp][0]);
                    mma16816(acc[i][jp * 2 + 1], ah, &bh[jp][2]);
                    mma16816(acc[i][jp * 2 + 0], ah, &bl[jp][0]);
                    mma16816(acc[i][jp * 2 + 1], ah, &bl[jp][2]);
                    if (terms == 3) {
                        mma16816(acc[i][jp * 2 + 0], al, &bh[jp][0]);
                        mma16816(acc[i][jp * 2 + 1], al, &bh[jp][2]);
                    }
                }
            }
        }
        __syncthreads();

        if (ic + 2 < nchunk) {
            const uint32_t stw = sb0 + p * STAGE_E * 2;
            const int k0 = (ic + 2) * KC;
            #pragma unroll
            for (int pl = 0; pl < 4; pl++) {
                if (pl == 1 && terms == 2) continue;
                #pragma unroll
                for (int h = 0; h < 4; h++) {
                    const int r = rowb + h * 32;
                    cpasync16(stw + (pl * PLANE_E + r * RS + jj) * 2,
                              gsrc[pl] + (long long)(rbase[pl] + r) * K + k0 + jj);
                }
            }
            cp_commit();
        }
    }

    // ---- epilogue
    const int lt = tid & 31;
    const int rr = lt >> 2;
    const int cc = (lt & 3) << 1;
    const int mbase = m0 + wm * 64 + rr;
    const int nbase = n0 + wn * 64 + cc;

    #pragma unroll
    for (int i = 0; i < 4; i++) {
        #pragma unroll
        for (int j = 0; j < 8; j++) {
            const int mr = mbase + i * 16;
            const int nc = nbase + j * 8;
            if (mode == 0) {
                const float b0 = bias[nc], b1 = bias[nc + 1];
                #pragma unroll
                for (int h = 0; h < 2; h++) {
                    const float x0 = acc[i][j][2 * h]     + b0;
                    const float x1 = acc[i][j][2 * h + 1] + b1;
                    __half h0 = __float2half_rn(x0);
                    __half h1 = __float2half_rn(x1);
                    __half l0 = __float2half_rn(x0 - __half2float(h0));
                    __half l1 = __float2half_rn(x1 - __half2float(h1));
                    const long long o = (long long)(mr + 8 * h) * N + nc;
                    *(uint32_t*)(outH + o) = (uint32_t)__half_as_ushort(h0) |
                                             ((uint32_t)__half_as_ushort(h1) << 16);
                    *(uint32_t*)(outL + o) = (uint32_t)__half_as_ushort(l0) |
                                             ((uint32_t)__half_as_ushort(l1) << 16);
                }
            } else {
                #pragma unroll
                for (int h = 0; h < 2; h++) {
                    float2 v;
                    v.x = acc[i][j][2 * h]     * scale;
                    v.y = acc[i][j][2 * h + 1] * scale;
                    *(float2*)(outF + (long long)(mr + 8 * h) * N + nc) = v;
                }
            }
        }
    }
}

// ---------------- elementwise: fp32 -> fp16 hi/lo split ------------------------
__global__ __launch_bounds__(256)
void k_split(const float* __restrict__ x, __half* __restrict__ h,
             __half* __restrict__ l, long long n)
{
    long long i = ((long long)blockIdx.x * blockDim.x + threadIdx.x) * 4;
    if (i >= n) return;
    float4 v = *(const float4*)(x + i);
    __half h0 = __float2half_rn(v.x), h1 = __float2half_rn(v.y);
    __half h2 = __float2half_rn(v.z), h3 = __float2half_rn(v.w);
    __half l0 = __float2half_rn(v.x - __half2float(h0));
    __half l1 = __float2half_rn(v.y - __half2float(h1));
    __half l2 = __float2half_rn(v.z - __half2float(h2));
    __half l3 = __float2half_rn(v.w - __half2float(h3));
    uint2 hv, lv;
    hv.x = (uint32_t)__half_as_ushort(h0) | ((uint32_t)__half_as_ushort(h1) << 16);
    hv.y = (uint32_t)__half_as_ushort(h2) | ((uint32_t)__half_as_ushort(h3) << 16);
    lv.x = (uint32_t)__half_as_ushort(l0) | ((uint32_t)__half_as_ushort(l1) << 16);
    lv.y = (uint32_t)__half_as_ushort(l2) | ((uint32_t)__half_as_ushort(l3) << 16);
    *(uint2*)(h + i) = hv;
    *(uint2*)(l + i) = lv;
}

// ---------------- pack 3 bias vectors into one stacked buffer ------------------
__global__ __launch_bounds__(1024)
void k_pack_bias(const float* __restrict__ bq, const float* __restrict__ bk,
                 const float* __restrict__ bv, float* __restrict__ dst)
{
    const int i = threadIdx.x;
    dst[i] = bq[i];
    dst[HID + i] = bk[i];
    dst[2 * HID + i] = bv[i];
}

// ---------------- dual-plane fp16 transpose: [z][R][C] -> [z][C][R] ------------
__global__ __launch_bounds__(256)
void k_tr_f16_2(const __half* __restrict__ inH, const __half* __restrict__ inL,
                __half* __restrict__ outH, __half* __restrict__ outL,
                int R, int C)
{
    __shared__ __half th[32][33];
    __shared__ __half tl[32][33];
    const int c0 = blockIdx.x * 32, r0 = blockIdx.y * 32;
    const int tx = threadIdx.x, ty = threadIdx.y;
    const long long zb = (long long)blockIdx.z * R * C;
    #pragma unroll
    for (int k = 0; k < 4; k++) {
        const long long idx = zb + (long long)(r0 + ty + k * 8) * C + c0 + tx;
        th[ty + k * 8][tx] = inH[idx];
        tl[ty + k * 8][tx] = inL[idx];
    }
    __syncthreads();
    #pragma unroll
    for (int k = 0; k < 4; k++) {
        const long long o = zb + (long long)(c0 + ty + k * 8) * R + r0 + tx;
        outH[o] = th[tx][ty + k * 8];
        outL[o] = tl[tx][ty + k * 8];
    }
}

// ---------------- softmax pass 1: per-(b,kq) max + inv-sum over S --------------
__global__ __launch_bounds__(256)
void softmax_stats(const float* __restrict__ attn,
                   float* __restrict__ statM, float* __restrict__ statI)
{
    const int c    = threadIdx.x & 63;
    const int lane = threadIdx.x >> 6;
    const int kq   = blockIdx.x * 64 + c;
    const long long base = (long long)blockIdx.y * SEQL * KQL + kq;
    const int CH = SEQL / 4;
    const int s0 = lane * CH;

    float m = -1e30f, lsum = 0.0f;
    for (int s = 0; s < CH; s++) {
        float x = attn[base + (long long)(s0 + s) * KQL];
        float nm = fmaxf(m, x);
        lsum = lsum * __expf(m - nm) + __expf(x - nm);
        m = nm;
    }
    __shared__ float sm[4][64];
    __shared__ float sl[4][64];
    sm[lane][c] = m;
    sl[lane][c] = lsum;
    __syncthreads();
    if (lane == 0) {
        float M = fmaxf(fmaxf(sm[0][c], sm[1][c]), fmaxf(sm[2][c], sm[3][c]));
        float L = sl[0][c] * __expf(sm[0][c] - M) + sl[1][c] * __expf(sm[1][c] - M)
                + sl[2][c] * __expf(sm[2][c] - M) + sl[3][c] * __expf(sm[3][c] - M);
        statM[(long long)blockIdx.y * KQL + kq] = M;
        statI[(long long)blockIdx.y * KQL + kq] = 1.0f / L;
    }
}

// ---------------- softmax pass 2 fused: normalize in place + transpose (hi only)
__global__ __launch_bounds__(256)
void k_norm_tr(float* __restrict__ attn,
               const float* __restrict__ statM, const float* __restrict__ statI,
               __half* __restrict__ h)
{
    __shared__ float t[32][33];
    const int kq0 = blockIdx.x * 32, s0 = blockIdx.y * 32;
    const int tx = threadIdx.x, ty = threadIdx.y;
    float* ip = attn + (long long)blockIdx.z * SEQL * KQL;
    __half* hp = h + (long long)blockIdx.z * KQL * SEQL;

    const float M = statM[(long long)blockIdx.z * KQL + kq0 + tx];
    const float I = statI[(long long)blockIdx.z * KQL + kq0 + tx];

    #pragma unroll
    for (int k = 0; k < 4; k++) {
        const long long idx = (long long)(s0 + ty + k * 8) * KQL + kq0 + tx;
        float p = __expf(ip[idx] - M) * I;
        ip[idx] = p;
        t[ty + k * 8][tx] = p;
    }
    __syncthreads();
    #pragma unroll
    for (int k = 0; k < 4; k++) {
        float x = t[tx][ty + k * 8];
        long long o = (long long)(kq0 + ty + k * 8) * SEQL + s0 + tx;
        hp[o] = __float2half_rn(x);
    }
}

// ---------------- launch -------------------------------------------------------
extern "C" void kernel_launch(void* const* d_in, const int* in_sizes, int n_in,
                              void* d_out, int out_size)
{
    const float* queries = (const float*)d_in[0];
    const float* keys    = (const float*)d_in[1];
    const float* values  = (const float*)d_in[2];
    const float* Wq      = (const float*)d_in[3];
    const float* bq      = (const float*)d_in[4];
    const float* Wk      = (const float*)d_in[5];
    const float* bk      = (const float*)d_in[6];
    const float* Wv      = (const float*)d_in[7];
    const float* bv      = (const float*)d_in[8];

    float* ctx  = (float*)d_out;
    float* attn = (float*)d_out + NT;

    __half *xh, *xl, *wh, *wl, *qkvh, *qkvl, *vth, *vtl, *ath;
    float *bias, *statM, *statI;
    cudaGetSymbolAddress((void**)&xh, g_xh);     cudaGetSymbolAddress((void**)&xl, g_xl);
    cudaGetSymbolAddress((void**)&wh, g_wh);     cudaGetSymbolAddress((void**)&wl, g_wl);
    cudaGetSymbolAddress((void**)&qkvh, g_qkvh); cudaGetSymbolAddress((void**)&qkvl, g_qkvl);
    cudaGetSymbolAddress((void**)&vth, g_vth);   cudaGetSymbolAddress((void**)&vtl, g_vtl);
    cudaGetSymbolAddress((void**)&ath, g_ath);
    cudaGetSymbolAddress((void**)&bias, g_bias);
    cudaGetSymbolAddress((void**)&statM, g_statM);
    cudaGetSymbolAddress((void**)&statI, g_statI);

    cudaFuncSetAttribute(gemm_mma, cudaFuncAttributeMaxDynamicSharedMemorySize, GEMM_SMEM);

    dim3 b256(256);
    dim3 b128(128);
    dim3 trb(32, 8);

    // ---- convert inputs + weights to stacked fp16 hi/lo planes
    k_split<<<(unsigned)(NT / 1024), b256>>>(queries, xh,          xl,          NT);
    k_split<<<(unsigned)(NT / 1024), b256>>>(keys,    xh + NT,     xl + NT,     NT);
    k_split<<<(unsigned)(NT / 1024), b256>>>(values,  xh + 2 * NT, xl + 2 * NT, NT);
    k_split<<<(unsigned)(NW / 1024), b256>>>(Wq, wh,          wl,          NW);
    k_split<<<(unsigned)(NW / 1024), b256>>>(Wk, wh + NW,     wl + NW,     NW);
    k_split<<<(unsigned)(NW / 1024), b256>>>(Wv, wh + 2 * NW, wl + 2 * NW, NW);
    k_pack_bias<<<1, 1024>>>(bq, bk, bv, bias);

    // ---- merged Q/K/V projection (z = 0,1,2), 3-term
    gemm_mma<<<dim3(HID / 128, (BATCH * KQL) / 128, 3), b128, GEMM_SMEM>>>(
        xh, xl, wh, wl, bias, nullptr, qkvh, qkvl,
        BATCH * KQL, HID, HID, 1.0f, 0, 3,
        (long long)NT, (long long)NW, (long long)NT, (long long)HID);

    const __half* qh = qkvh;              const __half* ql = qkvl;
    const __half* kh = qkvh + NT;         const __half* kl = qkvl + NT;
    const __half* vh = qkvh + 2 * NT;     const __half* vl = qkvl + 2 * NT;

    // ---- v transpose [b][s][h] -> [b][h][s] (both planes, one launch)
    k_tr_f16_2<<<dim3(HID / 32, SEQL / 32, BATCH), trb>>>(vh, vl, vth, vtl, SEQL, HID);

    // ---- scores[b][s][kq] = (k . q) / 32, straight into d_out attn, 3-term
    gemm_mma<<<dim3(KQL / 128, SEQL / 128, BATCH), b128, GEMM_SMEM>>>(
        kh, kl, qh, ql, nullptr, attn, nullptr, nullptr,
        SEQL, KQL, HID, 0.03125f, 1, 3,
        (long long)SEQL * HID, (long long)KQL * HID, (long long)SEQL * KQL, 0);

    // ---- softmax stats, then fused normalize + transpose (hi plane only)
    softmax_stats<<<dim3(KQL / 64, BATCH), b256>>>(attn, statM, statI);
    k_norm_tr<<<dim3(KQL / 32, SEQL / 32, BATCH), trb>>>(attn, statM, statI, ath);

    // ---- context[b][kq][h] = sum_s attnT[kq][s] * vT[h][s], 2-term (A hi only)
    gemm_mma<<<dim3(HID / 128, KQL / 128, BATCH), b128, GEMM_SMEM>>>(
        ath, nullptr, vth, vtl, nullptr, ctx, nullptr, nullptr,
        KQL, HID, SEQL, 1.0f, 2, 2,
        (long long)KQL * SEQL, (long long)HID * SEQL, (long long)KQL * HID, 0);
}